// round 5
// baseline (speedup 1.0000x reference)
#include <cuda_runtime.h>
#include <math.h>
#include <cstdint>

#define BB 8
#define NN 2048
#define CC 512
#define KK 8
#define EPSF 1e-6f
#define GENO_RATIO 0.1f

// ---------------- scratch ----------------
__device__ int   g_cnt[BB][KK];
__device__ int   g_idx[BB][KK][NN];
__device__ float g_wgt[BB][KK][NN];
__device__ float g_mass[BB][KK];
__device__ float g_hw[BB][KK][CC];
__device__ float g_glog[BB][KK];
__device__ float g_xtf[BB * NN * CC];   // tokens rounded to tf32 (33.5MB)
__device__ float g_w1tf[KK * CC * CC];  // w1 rounded to tf32 (8MB)

__device__ __forceinline__ uint32_t smem_u32(const void* p) {
    uint32_t a;
    asm("{ .reg .u64 t; cvta.to.shared.u64 t, %1; cvt.u32.u64 %0, t; }" : "=r"(a) : "l"(p));
    return a;
}
__device__ __forceinline__ float tf32r(float x) {
    uint32_t u;
    asm("cvt.rna.tf32.f32 %0, %1;" : "=r"(u) : "f"(x));
    return __uint_as_float(u);
}

// ---------------- prep: round w1, zero hw, cnt/mass/glog ----------------
__global__ __launch_bounds__(256) void prep_kernel(const float* __restrict__ w1,
                                                   const float* __restrict__ geno_vec,
                                                   const float* __restrict__ geno_w,
                                                   const float* __restrict__ geno_b) {
    int bid = blockIdx.x;
    if (bid < 512) {  // round w1: 512 blocks x 256 threads x 16 elems = 2M
        int base = bid * 4096 + threadIdx.x * 4;
#pragma unroll
        for (int i = 0; i < 4; i++) {
            float4 v = *(const float4*)(w1 + base + i * 1024);
            v.x = tf32r(v.x); v.y = tf32r(v.y); v.z = tf32r(v.z); v.w = tf32r(v.w);
            *(float4*)(g_w1tf + base + i * 1024) = v;
        }
    } else if (bid < 544) {  // zero hw
        int t = (bid - 512) * 256 + threadIdx.x;
        float* hw = &g_hw[0][0][0];
#pragma unroll
        for (int i = 0; i < 4; i++) hw[t + i * 8192] = 0.f;
    } else {
        int t = threadIdx.x;
        if (t < BB * KK) {
            ((int*)g_cnt)[t] = 0;
            ((float*)g_mass)[t] = 0.f;
            int b = t / KK, k = t % KK;
            float acc = 0.f;
            for (int c = 0; c < CC; c++) acc += geno_vec[b * CC + c] * geno_w[c * KK + k];
            g_glog[b][k] = GENO_RATIO * (acc + geno_b[k]);
        }
    }
}

// ---------------- gating (+ fused token tf32 rounding) ----------------
__global__ __launch_bounds__(256) void gate_kernel(const float* __restrict__ tokens,
                                                   const float* __restrict__ gate_w,
                                                   const float* __restrict__ gate_b) {
    __shared__ float gwT[KK][CC];
    int tid = threadIdx.x;
    for (int i = tid; i < CC * KK; i += 256) gwT[i & 7][i >> 3] = gate_w[i];
    __syncthreads();

    int warp = blockIdx.x * 8 + (tid >> 5);
    int lane = tid & 31;
    if (warp >= BB * NN) return;
    int b = warp / NN, n = warp % NN;
    const size_t row = (size_t)(b * NN + n) * CC;
    const float* x = tokens + row;
    float* xo = g_xtf + row;

    float acc[KK];
#pragma unroll
    for (int k = 0; k < KK; k++) acc[k] = 0.f;
#pragma unroll
    for (int i = 0; i < 4; i++) {
        int c = i * 128 + lane * 4;
        float4 xv = *(const float4*)(x + c);
        float4 xr;
        xr.x = tf32r(xv.x); xr.y = tf32r(xv.y); xr.z = tf32r(xv.z); xr.w = tf32r(xv.w);
        *(float4*)(xo + c) = xr;
#pragma unroll
        for (int k = 0; k < KK; k++) {
            float4 gv = *(const float4*)&gwT[k][c];
            acc[k] += xv.x * gv.x + xv.y * gv.y + xv.z * gv.z + xv.w * gv.w;
        }
    }
#pragma unroll
    for (int k = 0; k < KK; k++) {
#pragma unroll
        for (int off = 16; off; off >>= 1)
            acc[k] += __shfl_xor_sync(0xffffffffu, acc[k], off);
    }

    if (lane == 0) {
        float lg[KK];
#pragma unroll
        for (int k = 0; k < KK; k++) lg[k] = acc[k] + gate_b[k] + g_glog[b][k];
        int i0 = 0; float v0 = lg[0];
#pragma unroll
        for (int k = 1; k < KK; k++) if (lg[k] > v0) { v0 = lg[k]; i0 = k; }
        int i1 = -1; float v1 = -3.4e38f;
#pragma unroll
        for (int k = 0; k < KK; k++) if (k != i0 && lg[k] > v1) { v1 = lg[k]; i1 = k; }
        float e1 = __expf(v1 - v0);
        float inv = 1.f / (1.f + e1);
        float w0 = fmaxf(inv, EPSF), w1v = fmaxf(e1 * inv, EPSF);
        float s = 1.f / (w0 + w1v);
        w0 *= s; w1v *= s;
        int p0 = atomicAdd(&g_cnt[b][i0], 1);
        g_idx[b][i0][p0] = n; g_wgt[b][i0][p0] = w0;
        atomicAdd(&g_mass[b][i0], w0);
        int p1 = atomicAdd(&g_cnt[b][i1], 1);
        g_idx[b][i1][p1] = n; g_wgt[b][i1][p1] = w1v;
        atomicAdd(&g_mass[b][i1], w1v);
    }
}

// ---------------- ffn1: cp.async pipeline + 64x64 warp tiles ----------------
#define BM 128
#define BN 128
#define BKC 32
#define NSTAGE (CC / BKC)       // 16
#define XS_STR 36
#define WS_STR 136
#define X_TILE_B (BM * XS_STR * 4)
#define W_TILE_B (BKC * WS_STR * 4)
#define STAGE_B (X_TILE_B + W_TILE_B)
#define SMEM_TOTAL (2 * STAGE_B + BM * 4)

__device__ __forceinline__ void mma1688(float* c, const uint32_t* a, const uint32_t* bf) {
    asm volatile(
        "mma.sync.aligned.m16n8k8.row.col.f32.tf32.tf32.f32 "
        "{%0,%1,%2,%3}, {%4,%5,%6,%7}, {%8,%9}, {%0,%1,%2,%3};"
        : "+f"(c[0]), "+f"(c[1]), "+f"(c[2]), "+f"(c[3])
        : "r"(a[0]), "r"(a[1]), "r"(a[2]), "r"(a[3]), "r"(bf[0]), "r"(bf[1]));
}
__device__ __forceinline__ void cpasync16(uint32_t dst, const void* src, uint32_t sz) {
    asm volatile("cp.async.cg.shared.global [%0], [%1], 16, %2;" :: "r"(dst), "l"(src), "r"(sz));
}
__device__ __forceinline__ void cpasync16f(uint32_t dst, const void* src) {
    asm volatile("cp.async.cg.shared.global [%0], [%1], 16;" :: "r"(dst), "l"(src));
}

__global__ __launch_bounds__(128, 2) void ffn1_mma_kernel(const float* __restrict__ b1) {
    extern __shared__ char smem[];
    const int bk = blockIdx.z;
    const int b = bk >> 3, k = bk & 7;
    const int cnt = g_cnt[b][k];
    const int m0 = blockIdx.y * BM;
    if (m0 >= cnt) return;
    const int d0 = blockIdx.x * BN;

    float* Xsf[2] = { (float*)smem, (float*)(smem + STAGE_B) };
    float* Wsf[2] = { (float*)(smem + X_TILE_B), (float*)(smem + STAGE_B + X_TILE_B) };
    float* wt_s = (float*)(smem + 2 * STAGE_B);

    const int tid = threadIdx.x;
    const int lane = tid & 31, wid = tid >> 5;
    const int wm = wid >> 1, wn = wid & 1;
    const int l4 = lane >> 2, lm = lane & 3;

    const int m = m0 + tid;
    const bool valid = (m < cnt);
    const int n = valid ? g_idx[b][k][m] : 0;
    wt_s[tid] = valid ? g_wgt[b][k][m] : 0.f;
    const uint32_t xsz = valid ? 16u : 0u;

    const float* xg = g_xtf + ((size_t)(b * NN + n)) * CC;
    const float* wg = g_w1tf + ((size_t)k * CC + (tid >> 2)) * CC + d0 + (tid & 3) * 32;

    const uint32_t xs_dst0 = smem_u32(Xsf[0]) + tid * (XS_STR * 4);
    const uint32_t xs_dst1 = smem_u32(Xsf[1]) + tid * (XS_STR * 4);
    const uint32_t ws_dst0 = smem_u32(Wsf[0]) + (tid >> 2) * (WS_STR * 4) + (tid & 3) * 128;
    const uint32_t ws_dst1 = smem_u32(Wsf[1]) + (tid >> 2) * (WS_STR * 4) + (tid & 3) * 128;

#define ISSUE_STAGE(s, buf) do {                                                  \
        const float* xp_ = xg + (s) * BKC;                                        \
        const float* wp_ = wg + (size_t)(s) * BKC * CC;                           \
        uint32_t xd_ = (buf) ? xs_dst1 : xs_dst0;                                 \
        uint32_t wd_ = (buf) ? ws_dst1 : ws_dst0;                                 \
        _Pragma("unroll")                                                         \
        for (int j = 0; j < 8; j++) cpasync16(xd_ + j * 16, xp_ + j * 4, xsz);    \
        _Pragma("unroll")                                                         \
        for (int j = 0; j < 8; j++) cpasync16f(wd_ + j * 16, wp_ + j * 4);        \
        asm volatile("cp.async.commit_group;" ::: "memory");                      \
    } while (0)

    float acc[4][8][4];
#pragma unroll
    for (int mf = 0; mf < 4; mf++)
#pragma unroll
        for (int nf = 0; nf < 8; nf++)
#pragma unroll
            for (int q = 0; q < 4; q++) acc[mf][nf][q] = 0.f;

    ISSUE_STAGE(0, 0);

    for (int s = 0; s < NSTAGE; s++) {
        if (s + 1 < NSTAGE) {
            ISSUE_STAGE(s + 1, (s + 1) & 1);
            asm volatile("cp.async.wait_group 1;" ::: "memory");
        } else {
            asm volatile("cp.async.wait_group 0;" ::: "memory");
        }
        __syncthreads();

        const float* X = Xsf[s & 1];
        const float* W = Wsf[s & 1];
#pragma unroll
        for (int kk = 0; kk < 4; kk++) {
            const int ck = kk * 8;
            uint32_t a[4][4];
#pragma unroll
            for (int mf = 0; mf < 4; mf++) {
                const float* xr = X + (wm * 64 + mf * 16 + l4) * XS_STR + ck + lm;
                a[mf][0] = __float_as_uint(xr[0]);
                a[mf][1] = __float_as_uint(xr[8 * XS_STR]);
                a[mf][2] = __float_as_uint(xr[4]);
                a[mf][3] = __float_as_uint(xr[8 * XS_STR + 4]);
            }
            uint32_t bfr[8][2];
#pragma unroll
            for (int nf = 0; nf < 8; nf++) {
                const int col = wn * 64 + nf * 8 + l4;
                bfr[nf][0] = __float_as_uint(W[(ck + lm) * WS_STR + col]);
                bfr[nf][1] = __float_as_uint(W[(ck + lm + 4) * WS_STR + col]);
            }
#pragma unroll
            for (int mf = 0; mf < 4; mf++)
#pragma unroll
                for (int nf = 0; nf < 8; nf++)
                    mma1688(acc[mf][nf], a[mf], bfr[nf]);
        }
        __syncthreads();
    }

    float part[8][2];
#pragma unroll
    for (int nf = 0; nf < 8; nf++) { part[nf][0] = 0.f; part[nf][1] = 0.f; }

    float bias[8][2];
#pragma unroll
    for (int nf = 0; nf < 8; nf++)
#pragma unroll
        for (int j = 0; j < 2; j++)
            bias[nf][j] = __ldg(b1 + k * CC + d0 + wn * 64 + nf * 8 + lm * 2 + j);

#pragma unroll
    for (int mf = 0; mf < 4; mf++) {
        const int r0 = wm * 64 + mf * 16 + l4;
        const float w0 = wt_s[r0], w1r = wt_s[r0 + 8];
#pragma unroll
        for (int nf = 0; nf < 8; nf++)
#pragma unroll
            for (int j = 0; j < 2; j++)
                part[nf][j] += fmaxf(acc[mf][nf][j] + bias[nf][j], 0.f) * w0
                             + fmaxf(acc[mf][nf][2 + j] + bias[nf][j], 0.f) * w1r;
    }
#pragma unroll
    for (int off = 4; off < 32; off <<= 1)
#pragma unroll
        for (int nf = 0; nf < 8; nf++)
#pragma unroll
            for (int j = 0; j < 2; j++)
                part[nf][j] += __shfl_xor_sync(0xffffffffu, part[nf][j], off);

    if (l4 == 0) {
        float* hw = &g_hw[b][k][0];
#pragma unroll
        for (int nf = 0; nf < 8; nf++)
#pragma unroll
            for (int j = 0; j < 2; j++)
                atomicAdd(hw + d0 + wn * 64 + nf * 8 + lm * 2 + j, part[nf][j]);
    }
}

// ---------------- centers: batched over b, w2 read once ----------------
__global__ __launch_bounds__(256) void centers_kernel(const float* __restrict__ w2,
                                                      const float* __restrict__ b2,
                                                      float* __restrict__ out, int out_size) {
    const int k = blockIdx.x;        // 0..7
    const int e0 = blockIdx.y * 32;  // 16 tiles
    __shared__ float hw_s[BB][CC];       // 16KB
    __shared__ float part[8][32][9];     // padded: conflict-free
    const int tid = threadIdx.x;

    for (int i = tid; i < BB * CC; i += 256)
        hw_s[i >> 9][i & 511] = g_hw[i >> 9][k][i & 511];
    __syncthreads();

    const int e = e0 + (tid & 31);
    const int ds = (tid >> 5) * 64;
    float acc[BB];
#pragma unroll
    for (int b = 0; b < BB; b++) acc[b] = 0.f;

    const float* w2p = w2 + ((size_t)k * CC + ds) * CC + e;
#pragma unroll 4
    for (int d = 0; d < 64; d++) {
        float w = w2p[(size_t)d * CC];
#pragma unroll
        for (int b = 0; b < BB; b++) acc[b] += hw_s[b][ds + d] * w;
    }
#pragma unroll
    for (int b = 0; b < BB; b++) part[tid >> 5][tid & 31][b] = acc[b];
    __syncthreads();

    {
        const int b = tid >> 5, el = tid & 31;
        float s = 0.f;
#pragma unroll
        for (int sl = 0; sl < 8; sl++) s += part[sl][el][b];
        float mass = g_mass[b][k];
        float inv = 1.f / fmaxf(mass, EPSF);
        float val = (s + b2[k * CC + e0 + el] * mass) * inv;
        int o = (b * KK + k) * CC + e0 + el;
        if (o < out_size) out[o] = val;
    }

    if (blockIdx.x == 0 && blockIdx.y == 0 && tid == 0) {
        float usage[KK], mean = 0.f;
#pragma unroll
        for (int kk = 0; kk < KK; kk++) {
            int s = 0;
            for (int bb = 0; bb < BB; bb++) s += g_cnt[bb][kk];
            usage[kk] = (float)s / (float)(BB * NN);
            mean += usage[kk];
        }
        mean /= (float)KK;
        float var = 0.f;
#pragma unroll
        for (int kk = 0; kk < KK; kk++) { float d = usage[kk] - mean; var += d * d; }
        var /= (float)KK;
        float denom = mean + EPSF;
        out[out_size - 1] = var / (denom * denom);
    }
}

// ---------------- launch ----------------
extern "C" void kernel_launch(void* const* d_in, const int* in_sizes, int n_in,
                              void* d_out, int out_size) {
    const float* tokens   = (const float*)d_in[0];
    const float* geno_vec = (const float*)d_in[1];
    const float* gate_w   = (const float*)d_in[2];
    const float* gate_b   = (const float*)d_in[3];
    const float* geno_w   = (const float*)d_in[4];
    const float* geno_b   = (const float*)d_in[5];
    const float* w1       = (const float*)d_in[6];
    const float* b1       = (const float*)d_in[7];
    const float* w2       = (const float*)d_in[8];
    const float* b2       = (const float*)d_in[9];
    float* out = (float*)d_out;

    cudaFuncSetAttribute(ffn1_mma_kernel, cudaFuncAttributeMaxDynamicSharedMemorySize, SMEM_TOTAL);

    prep_kernel<<<545, 256>>>(w1, geno_vec, geno_w, geno_b);
    gate_kernel<<<(BB * NN + 7) / 8, 256>>>(tokens, gate_w, gate_b);
    {
        dim3 g(CC / BN, NN / BM, BB * KK);
        ffn1_mma_kernel<<<g, 128, SMEM_TOTAL>>>(b1);
    }
    {
        dim3 g(KK, CC / 32);
        centers_kernel<<<g, 256>>>(w2, b2, out, out_size);
    }
}

// round 7
// speedup vs baseline: 1.1901x; 1.1901x over previous
#include <cuda_runtime.h>
#include <math.h>
#include <cstdint>

#define BB 8
#define NN 2048
#define CC 512
#define KK 8
#define EPSF 1e-6f
#define GENO_RATIO 0.1f

// ---------------- scratch ----------------
__device__ int   g_cnt[BB][KK];
__device__ int   g_idx[BB][KK][NN];
__device__ float g_wgt[BB][KK][NN];
__device__ float g_mass[BB][KK];
__device__ float g_hw[BB][KK][CC];
__device__ float g_glog[BB][KK];

__device__ __forceinline__ float tf32r(float x) {
    uint32_t u;
    asm("cvt.rna.tf32.f32 %0, %1;" : "=r"(u) : "f"(x));
    return __uint_as_float(u);
}

// ---------------- prep: zero hw/cnt/mass + glog ----------------
__global__ __launch_bounds__(256) void prep_kernel(const float* __restrict__ geno_vec,
                                                   const float* __restrict__ geno_w,
                                                   const float* __restrict__ geno_b) {
    if (blockIdx.x < 32) {
        int t = blockIdx.x * 256 + threadIdx.x;
        float* hw = &g_hw[0][0][0];
#pragma unroll
        for (int i = 0; i < 4; i++) hw[t + i * 8192] = 0.f;
    } else {
        int t = threadIdx.x;
        if (t < BB * KK) {
            ((int*)g_cnt)[t] = 0;
            ((float*)g_mass)[t] = 0.f;
            int b = t / KK, k = t % KK;
            float acc = 0.f;
            for (int c = 0; c < CC; c++) acc += geno_vec[b * CC + c] * geno_w[c * KK + k];
            g_glog[b][k] = GENO_RATIO * (acc + geno_b[k]);
        }
    }
}

// ---------------- gating ----------------
__global__ __launch_bounds__(256) void gate_kernel(const float* __restrict__ tokens,
                                                   const float* __restrict__ gate_w,
                                                   const float* __restrict__ gate_b) {
    __shared__ float gwT[KK][CC];
    int tid = threadIdx.x;
    for (int i = tid; i < CC * KK; i += 256) gwT[i & 7][i >> 3] = gate_w[i];
    __syncthreads();

    int warp = blockIdx.x * 8 + (tid >> 5);
    int lane = tid & 31;
    if (warp >= BB * NN) return;
    int b = warp / NN, n = warp % NN;
    const float* x = tokens + (size_t)(b * NN + n) * CC;

    float acc[KK];
#pragma unroll
    for (int k = 0; k < KK; k++) acc[k] = 0.f;
#pragma unroll
    for (int i = 0; i < 4; i++) {
        int c = i * 128 + lane * 4;
        float4 xv = *(const float4*)(x + c);
#pragma unroll
        for (int k = 0; k < KK; k++) {
            float4 gv = *(const float4*)&gwT[k][c];
            acc[k] += xv.x * gv.x + xv.y * gv.y + xv.z * gv.z + xv.w * gv.w;
        }
    }
#pragma unroll
    for (int k = 0; k < KK; k++) {
#pragma unroll
        for (int off = 16; off; off >>= 1)
            acc[k] += __shfl_xor_sync(0xffffffffu, acc[k], off);
    }

    if (lane == 0) {
        float lg[KK];
#pragma unroll
        for (int k = 0; k < KK; k++) lg[k] = acc[k] + gate_b[k] + g_glog[b][k];
        int i0 = 0; float v0 = lg[0];
#pragma unroll
        for (int k = 1; k < KK; k++) if (lg[k] > v0) { v0 = lg[k]; i0 = k; }
        int i1 = -1; float v1 = -3.4e38f;
#pragma unroll
        for (int k = 0; k < KK; k++) if (k != i0 && lg[k] > v1) { v1 = lg[k]; i1 = k; }
        float e1 = __expf(v1 - v0);
        float inv = 1.f / (1.f + e1);
        float w0 = fmaxf(inv, EPSF), w1v = fmaxf(e1 * inv, EPSF);
        float s = 1.f / (w0 + w1v);
        w0 *= s; w1v *= s;
        int p0 = atomicAdd(&g_cnt[b][i0], 1);
        g_idx[b][i0][p0] = n; g_wgt[b][i0][p0] = w0;
        atomicAdd(&g_mass[b][i0], w0);
        int p1 = atomicAdd(&g_cnt[b][i1], 1);
        g_idx[b][i1][p1] = n; g_wgt[b][i1][p1] = w1v;
        atomicAdd(&g_mass[b][i1], w1v);
    }
}

// ---------------- ffn1 via mma.sync tf32 (exact R3 structure, 183us proven) ------
#define BM 128
#define BN 128
#define BKC 32
#define NSTAGE (CC / BKC)     // 16
#define XS_STRIDE (BM + 8)    // 136 floats (k-major X tile)
#define WS_STRIDE (BN + 8)    // 136 floats (k-major W tile)
#define XTILE_FLOATS (BKC * XS_STRIDE)
#define WTILE_FLOATS (BKC * WS_STRIDE)
#define STAGE_FLOATS (XTILE_FLOATS + WTILE_FLOATS)

__device__ __forceinline__ void mma1688(float* c, const uint32_t* a, const uint32_t* bf) {
    asm volatile(
        "mma.sync.aligned.m16n8k8.row.col.f32.tf32.tf32.f32 "
        "{%0,%1,%2,%3}, {%4,%5,%6,%7}, {%8,%9}, {%0,%1,%2,%3};"
        : "+f"(c[0]), "+f"(c[1]), "+f"(c[2]), "+f"(c[3])
        : "r"(a[0]), "r"(a[1]), "r"(a[2]), "r"(a[3]), "r"(bf[0]), "r"(bf[1]));
}

__global__ __launch_bounds__(256, 1) void ffn1_mma_kernel(const float* __restrict__ tokens,
                                                          const float* __restrict__ w1,
                                                          const float* __restrict__ b1) {
    extern __shared__ float smem[];
    const int bk = blockIdx.z;
    const int b = bk >> 3, k = bk & 7;
    const int cnt = g_cnt[b][k];
    const int m0 = blockIdx.y * BM;
    if (m0 >= cnt) return;
    const int d0 = blockIdx.x * BN;

    float* Xs0 = smem;
    float* Ws0 = smem + XTILE_FLOATS;
    float* Xs1 = smem + STAGE_FLOATS;
    float* Ws1 = smem + STAGE_FLOATS + XTILE_FLOATS;
    int*   ns_s = (int*)(smem + 2 * STAGE_FLOATS);
    float* wt_s = (float*)(ns_s + BM);

    const int tid = threadIdx.x;
    const int lane = tid & 31, wid = tid >> 5;
    const int wm = wid >> 2, wn = wid & 3;     // 2 x 4 warp grid
    const int l4 = lane >> 2, lm = lane & 3;

    if (tid < BM) {
        int m = m0 + tid;
        if (m < cnt) { ns_s[tid] = g_idx[b][k][m]; wt_s[tid] = g_wgt[b][k][m]; }
        else         { ns_s[tid] = -1;             wt_s[tid] = 0.f; }
    }
    __syncthreads();

    const int xm = tid >> 1;              // token row 0..127
    const int xjb = (tid & 1) * 4;        // float4 index base (0 or 4)
    const int xn = ns_s[xm];
    const float* xp = (xn >= 0) ? tokens + ((size_t)(b * NN + xn)) * CC : nullptr;
    const int wr = tid >> 3;              // w row (c) 0..31
    const int wjb = tid & 7;              // float4 col base
    const float* wp = w1 + ((size_t)k * CC + wr) * CC + d0;

    float4 xv[4], wv[4];
#define LOAD_STAGE(s) do {                                                        \
        int c0_ = (s) * BKC;                                                      \
        _Pragma("unroll")                                                         \
        for (int i = 0; i < 4; i++)                                               \
            xv[i] = xp ? *(const float4*)(xp + c0_ + (xjb + i) * 4)               \
                       : make_float4(0.f, 0.f, 0.f, 0.f);                         \
        _Pragma("unroll")                                                         \
        for (int i = 0; i < 4; i++)                                               \
            wv[i] = *(const float4*)(wp + (size_t)c0_ * CC + (wjb + i * 8) * 4);  \
    } while (0)

#define STORE_STAGE(Xst, Wst) do {                                                \
        _Pragma("unroll")                                                         \
        for (int i = 0; i < 4; i++) {                                             \
            int kl = (xjb + i) * 4;                                               \
            (Xst)[(kl + 0) * XS_STRIDE + xm] = tf32r(xv[i].x);                    \
            (Xst)[(kl + 1) * XS_STRIDE + xm] = tf32r(xv[i].y);                    \
            (Xst)[(kl + 2) * XS_STRIDE + xm] = tf32r(xv[i].z);                    \
            (Xst)[(kl + 3) * XS_STRIDE + xm] = tf32r(xv[i].w);                    \
        }                                                                         \
        _Pragma("unroll")                                                         \
        for (int i = 0; i < 4; i++) {                                             \
            float4 t;                                                             \
            t.x = tf32r(wv[i].x); t.y = tf32r(wv[i].y);                           \
            t.z = tf32r(wv[i].z); t.w = tf32r(wv[i].w);                           \
            *(float4*)((Wst) + wr * WS_STRIDE + (wjb + i * 8) * 4) = t;           \
        }                                                                         \
    } while (0)

    float acc[4][4][4];
#pragma unroll
    for (int mf = 0; mf < 4; mf++)
#pragma unroll
        for (int nf = 0; nf < 4; nf++)
#pragma unroll
            for (int q = 0; q < 4; q++) acc[mf][nf][q] = 0.f;

    LOAD_STAGE(0);
    STORE_STAGE(Xs0, Ws0);
    __syncthreads();

    for (int s = 0; s < NSTAGE; s++) {
        const float* Xst = (s & 1) ? Xs1 : Xs0;
        const float* Wst = (s & 1) ? Ws1 : Ws0;
        if (s + 1 < NSTAGE) LOAD_STAGE(s + 1);

#pragma unroll
        for (int kk = 0; kk < 4; kk++) {
            uint32_t a[4][4], bf[4][2];
            const float* xk0 = Xst + (kk * 8 + lm) * XS_STRIDE;
            const float* xk4 = Xst + (kk * 8 + lm + 4) * XS_STRIDE;
#pragma unroll
            for (int mf = 0; mf < 4; mf++) {
                int mrow = wm * 64 + mf * 16 + l4;
                a[mf][0] = __float_as_uint(xk0[mrow]);
                a[mf][1] = __float_as_uint(xk0[mrow + 8]);
                a[mf][2] = __float_as_uint(xk4[mrow]);
                a[mf][3] = __float_as_uint(xk4[mrow + 8]);
            }
            const float* wk0 = Wst + (kk * 8 + lm) * WS_STRIDE;
            const float* wk4 = Wst + (kk * 8 + lm + 4) * WS_STRIDE;
#pragma unroll
            for (int nf = 0; nf < 4; nf++) {
                int ncol = wn * 32 + nf * 8 + l4;
                bf[nf][0] = __float_as_uint(wk0[ncol]);
                bf[nf][1] = __float_as_uint(wk4[ncol]);
            }
#pragma unroll
            for (int mf = 0; mf < 4; mf++)
#pragma unroll
                for (int nf = 0; nf < 4; nf++)
                    mma1688(acc[mf][nf], a[mf], bf[nf]);
        }

        if (s + 1 < NSTAGE) {
            __syncthreads();
            if (s & 1) STORE_STAGE(Xs0, Ws0);
            else       STORE_STAGE(Xs1, Ws1);
            __syncthreads();
        }
    }

    // epilogue: relu(acc + b1) * wt, reduce over token rows
    float bias[4][2];
#pragma unroll
    for (int nf = 0; nf < 4; nf++)
#pragma unroll
        for (int j = 0; j < 2; j++)
            bias[nf][j] = __ldg(b1 + k * CC + d0 + wn * 32 + nf * 8 + lm * 2 + j);

    float part[4][2];
#pragma unroll
    for (int nf = 0; nf < 4; nf++) { part[nf][0] = 0.f; part[nf][1] = 0.f; }

#pragma unroll
    for (int mf = 0; mf < 4; mf++) {
        int r0 = wm * 64 + mf * 16 + l4;
        float w0 = wt_s[r0], w1r = wt_s[r0 + 8];
#pragma unroll
        for (int nf = 0; nf < 4; nf++)
#pragma unroll
            for (int j = 0; j < 2; j++)
                part[nf][j] += fmaxf(acc[mf][nf][j] + bias[nf][j], 0.f) * w0
                             + fmaxf(acc[mf][nf][2 + j] + bias[nf][j], 0.f) * w1r;
    }
#pragma unroll
    for (int off = 4; off < 32; off <<= 1)
#pragma unroll
        for (int nf = 0; nf < 4; nf++)
#pragma unroll
            for (int j = 0; j < 2; j++)
                part[nf][j] += __shfl_xor_sync(0xffffffffu, part[nf][j], off);

    if (l4 == 0) {
        float* hw = &g_hw[b][k][0];
#pragma unroll
        for (int nf = 0; nf < 4; nf++)
#pragma unroll
            for (int j = 0; j < 2; j++)
                atomicAdd(hw + d0 + wn * 32 + nf * 8 + lm * 2 + j, part[nf][j]);
    }
}

// ---------------- centers: batched over b, w2 read once (+loss fused) ----------
__global__ __launch_bounds__(256) void centers_kernel(const float* __restrict__ w2,
                                                      const float* __restrict__ b2,
                                                      float* __restrict__ out, int out_size) {
    const int k = blockIdx.x;        // 0..7
    const int e0 = blockIdx.y * 32;  // 16 tiles
    __shared__ float hw_s[BB][CC];       // 16KB
    __shared__ float part[8][32][9];     // padded: conflict-free
    const int tid = threadIdx.x;

    for (int i = tid; i < BB * CC; i += 256)
        hw_s[i >> 9][i & 511] = g_hw[i >> 9][k][i & 511];
    __syncthreads();

    const int e = e0 + (tid & 31);
    const int ds = (tid >> 5) * 64;
    float acc[BB];
#pragma unroll
    for (int b = 0; b < BB; b++) acc[b] = 0.f;

    const float* w2p = w2 + ((size_t)k * CC + ds) * CC + e;
#pragma unroll 4
    for (int d = 0; d < 64; d++) {
        float w = w2p[(size_t)d * CC];
#pragma unroll
        for (int b = 0; b < BB; b++) acc[b] += hw_s[b][ds + d] * w;
    }
#pragma unroll
    for (int b = 0; b < BB; b++) part[tid >> 5][tid & 31][b] = acc[b];
    __syncthreads();

    {
        const int b = tid >> 5, el = tid & 31;
        float s = 0.f;
#pragma unroll
        for (int sl = 0; sl < 8; sl++) s += part[sl][el][b];
        float mass = g_mass[b][k];
        float inv = 1.f / fmaxf(mass, EPSF);
        float val = (s + b2[k * CC + e0 + el] * mass) * inv;
        int o = (b * KK + k) * CC + e0 + el;
        if (o < out_size) out[o] = val;
    }

    if (blockIdx.x == 0 && blockIdx.y == 0 && tid == 0) {
        float usage[KK], mean = 0.f;
#pragma unroll
        for (int kk = 0; kk < KK; kk++) {
            int s = 0;
            for (int bb = 0; bb < BB; bb++) s += g_cnt[bb][kk];
            usage[kk] = (float)s / (float)(BB * NN);
            mean += usage[kk];
        }
        mean /= (float)KK;
        float var = 0.f;
#pragma unroll
        for (int kk = 0; kk < KK; kk++) { float d = usage[kk] - mean; var += d * d; }
        var /= (float)KK;
        float denom = mean + EPSF;
        out[out_size - 1] = var / (denom * denom);
    }
}

// ---------------- launch ----------------
extern "C" void kernel_launch(void* const* d_in, const int* in_sizes, int n_in,
                              void* d_out, int out_size) {
    const float* tokens   = (const float*)d_in[0];
    const float* geno_vec = (const float*)d_in[1];
    const float* gate_w   = (const float*)d_in[2];
    const float* gate_b   = (const float*)d_in[3];
    const float* geno_w   = (const float*)d_in[4];
    const float* geno_b   = (const float*)d_in[5];
    const float* w1       = (const float*)d_in[6];
    const float* b1       = (const float*)d_in[7];
    const float* w2       = (const float*)d_in[8];
    const float* b2       = (const float*)d_in[9];
    float* out = (float*)d_out;

    const int smem_bytes = (2 * STAGE_FLOATS) * 4 + BM * 8;
    cudaFuncSetAttribute(ffn1_mma_kernel, cudaFuncAttributeMaxDynamicSharedMemorySize, smem_bytes);

    prep_kernel<<<33, 256>>>(geno_vec, geno_w, geno_b);
    gate_kernel<<<(BB * NN + 7) / 8, 256>>>(tokens, gate_w, gate_b);
    {
        dim3 g(CC / BN, NN / BM, BB * KK);  // 4 x 16 x 64
        ffn1_mma_kernel<<<g, 256, smem_bytes>>>(tokens, w1, b1);
    }
    {
        dim3 g(KK, CC / 32);
        centers_kernel<<<g, 256>>>(w2, b2, out, out_size);
    }
}